// round 2
// baseline (speedup 1.0000x reference)
#include <cuda_runtime.h>

#define T_STEPS 50
#define S_DIM   100
#define H_DIM   256
#define C_DIM   100
#define B_ROWS  4096
#define M_ROWS  16
#define N_CTA   (B_ROWS / M_ROWS)   // 256 CTAs
#define KC      32
#define WBUF    (256 * KC)          // one weight chunk: 256 rows x 32 k (floats)

__device__ float g_partials[N_CTA];

__device__ __forceinline__ float4 ldg4(const float* p) {
    return *reinterpret_cast<const float4*>(p);
}

// Load one KC-wide chunk of W[N][K] (row-major) into registers.
// thread t: 8 float4 loads; row n = (t>>3) + 32r, cols k0 + (t&7)*4 .. +3.
// Guards: k < KREAL (zero-fill K padding), n < NREAL (skip missing rows).
template<int KREAL, int NREAL>
__device__ __forceinline__ void ldw_chunk(const float* __restrict__ Wg, int k0,
                                          int tid, float4 pre[8]) {
    const int c4 = (tid & 7) << 2;
    const int nb = tid >> 3;
    const int k  = k0 + c4;
#pragma unroll
    for (int r = 0; r < 8; r++) {
        int n = nb + (r << 5);
        float4 v = make_float4(0.f, 0.f, 0.f, 0.f);
        bool ok = true;
        if (NREAL != 256) ok = ok && (n < NREAL);
        if ((KREAL % KC) != 0) ok = ok && (k < KREAL);
        if (ok) v = ldg4(Wg + n * KREAL + k);
        pre[r] = v;
    }
}

// Store prefetched chunk into smem with XOR swizzle: column quad k4 ^= (n>>2)&7.
// Per 8-lane STS.128 phase: one row, 8 distinct 16B columns -> conflict-free.
__device__ __forceinline__ void stw_chunk(float* __restrict__ wb, int tid,
                                          const float4 pre[8]) {
    const int c  = tid & 7;
    const int nb = tid >> 3;
#pragma unroll
    for (int r = 0; r < 8; r++) {
        int n   = nb + (r << 5);
        int col = ((c ^ ((n >> 2) & 7)) << 2);
        *reinterpret_cast<float4*>(wb + n * KC + col) = pre[r];
    }
}

// out[16][256] (row stride 256) = in[16][INSTRIDE] @ W[256][KREAL]^T
// Thread map: mt = tid>>6 (rows 4mt..4mt+3), ng = tid&63 (cols 4ng..4ng+3).
// All lanes of a warp share mt -> activation LDS.128 are pure broadcasts.
template<int CHUNKS, int KREAL, int INSTRIDE>
__device__ __forceinline__ void gemm_16x256(const float* __restrict__ in,
                                            const float* __restrict__ Wg,
                                            float* __restrict__ s_w,
                                            float* __restrict__ out, int tid) {
    const int mt = tid >> 6;
    const int ng = tid & 63;
    const int m0 = mt << 2;
    const int n0 = ng << 2;
    const int sw = ng & 7;
    float acc[4][4];
#pragma unroll
    for (int j = 0; j < 4; j++)
#pragma unroll
        for (int i = 0; i < 4; i++) acc[j][i] = 0.f;

    float4 pre[8];
    ldw_chunk<KREAL, 256>(Wg, 0, tid, pre);
    stw_chunk(s_w, tid, pre);
    __syncthreads();

#pragma unroll 1
    for (int cc = 0; cc < CHUNKS; cc++) {
        if (cc + 1 < CHUNKS) ldw_chunk<KREAL, 256>(Wg, (cc + 1) * KC, tid, pre);
        const float* wb  = s_w + (cc & 1) * WBUF;
        const float* inb = in + cc * KC;
#pragma unroll
        for (int k4 = 0; k4 < 8; k4++) {
            float4 xv[4];
            float4 wv[4];
#pragma unroll
            for (int j = 0; j < 4; j++)
                xv[j] = *reinterpret_cast<const float4*>(inb + (m0 + j) * INSTRIDE + (k4 << 2));
#pragma unroll
            for (int i = 0; i < 4; i++)
                wv[i] = *reinterpret_cast<const float4*>(wb + (n0 + i) * KC + ((k4 ^ sw) << 2));
#pragma unroll
            for (int j = 0; j < 4; j++)
#pragma unroll
                for (int i = 0; i < 4; i++) {
                    acc[j][i] = fmaf(xv[j].x, wv[i].x, acc[j][i]);
                    acc[j][i] = fmaf(xv[j].y, wv[i].y, acc[j][i]);
                    acc[j][i] = fmaf(xv[j].z, wv[i].z, acc[j][i]);
                    acc[j][i] = fmaf(xv[j].w, wv[i].w, acc[j][i]);
                }
        }
        if (cc + 1 < CHUNKS) stw_chunk(s_w + ((cc + 1) & 1) * WBUF, tid, pre);
        __syncthreads();
    }
#pragma unroll
    for (int j = 0; j < 4; j++) {
        float4 o = make_float4(acc[j][0], acc[j][1], acc[j][2], acc[j][3]);
        *reinterpret_cast<float4*>(out + (m0 + j) * 256 + n0) = o;
    }
}

// out[16][0..99] = in[16][256] @ Wo[100][256]^T
// Thread map: mt = tid>>5 (rows 2mt..2mt+1), ng = tid&31 (cols 4ng..4ng+3), active ng<25.
__device__ __forceinline__ void gemm_16x100(const float* __restrict__ in,
                                            const float* __restrict__ Wg,
                                            float* __restrict__ s_w,
                                            float* __restrict__ out, int tid) {
    const int mt = tid >> 5;
    const int ng = tid & 31;
    const int m0 = mt << 1;
    const int n0 = ng << 2;
    const int sw = ng & 7;
    const bool act = (ng < 25);
    float acc[2][4];
#pragma unroll
    for (int j = 0; j < 2; j++)
#pragma unroll
        for (int i = 0; i < 4; i++) acc[j][i] = 0.f;

    float4 pre[8];
    ldw_chunk<256, 100>(Wg, 0, tid, pre);
    stw_chunk(s_w, tid, pre);
    __syncthreads();

#pragma unroll 1
    for (int cc = 0; cc < 8; cc++) {
        if (cc + 1 < 8) ldw_chunk<256, 100>(Wg, (cc + 1) * KC, tid, pre);
        if (act) {
            const float* wb  = s_w + (cc & 1) * WBUF;
            const float* inb = in + cc * KC;
#pragma unroll
            for (int k4 = 0; k4 < 8; k4++) {
                float4 xv[2];
                float4 wv[4];
#pragma unroll
                for (int j = 0; j < 2; j++)
                    xv[j] = *reinterpret_cast<const float4*>(inb + (m0 + j) * 256 + (k4 << 2));
#pragma unroll
                for (int i = 0; i < 4; i++)
                    wv[i] = *reinterpret_cast<const float4*>(wb + (n0 + i) * KC + ((k4 ^ sw) << 2));
#pragma unroll
                for (int j = 0; j < 2; j++)
#pragma unroll
                    for (int i = 0; i < 4; i++) {
                        acc[j][i] = fmaf(xv[j].x, wv[i].x, acc[j][i]);
                        acc[j][i] = fmaf(xv[j].y, wv[i].y, acc[j][i]);
                        acc[j][i] = fmaf(xv[j].z, wv[i].z, acc[j][i]);
                        acc[j][i] = fmaf(xv[j].w, wv[i].w, acc[j][i]);
                    }
            }
        }
        if (cc + 1 < 8) stw_chunk(s_w + ((cc + 1) & 1) * WBUF, tid, pre);
        __syncthreads();
    }
    if (act) {
#pragma unroll
        for (int j = 0; j < 2; j++) {
            float4 o = make_float4(acc[j][0], acc[j][1], acc[j][2], acc[j][3]);
            *reinterpret_cast<float4*>(out + (m0 + j) * 256 + n0) = o;
        }
    }
}

// Fused bias + LayerNorm + gamma/beta + relu.
// 16 lanes per row (r = tid>>4, l = tid&15), shfl_xor reductions within 16-lane groups.
__device__ __forceinline__ void ln_relu(const float* __restrict__ y,
                                        float* __restrict__ xo,
                                        const float* __restrict__ bias,
                                        const float* __restrict__ gamma,
                                        const float* __restrict__ beta,
                                        int r, int l) {
    float v[16];
    float sum = 0.f, sq = 0.f;
#pragma unroll
    for (int i = 0; i < 16; i++) {
        int h = l + (i << 4);
        float tv = y[r * 256 + h] + bias[h];
        v[i] = tv;
        sum += tv;
        sq = fmaf(tv, tv, sq);
    }
#pragma unroll
    for (int o = 8; o >= 1; o >>= 1) {
        sum += __shfl_xor_sync(0xffffffffu, sum, o);
        sq  += __shfl_xor_sync(0xffffffffu, sq, o);
    }
    float mean = sum * (1.f / 256.f);
    float var  = sq * (1.f / 256.f) - mean * mean;
    float rstd = rsqrtf(var + 1e-5f);
#pragma unroll
    for (int i = 0; i < 16; i++) {
        int h = l + (i << 4);
        float xn = (v[i] - mean) * rstd * gamma[h] + beta[h];
        xo[r * 256 + h] = fmaxf(xn, 0.f);
    }
}

__global__ void __launch_bounds__(256, 2)
model_kernel(const float* __restrict__ s0, const float* __restrict__ prices,
             const float* __restrict__ W1, const float* __restrict__ b1,
             const float* __restrict__ g1, const float* __restrict__ be1,
             const float* __restrict__ W2, const float* __restrict__ b2,
             const float* __restrict__ g2, const float* __restrict__ be2,
             const float* __restrict__ Wo, const float* __restrict__ bo) {
    extern __shared__ float sm[];
    float* s_w    = sm;                        // 2 * 8192
    float* s_s    = sm + 2 * WBUF;             // 16 x 128 (cols 100..127 zero)
    float* s_x    = s_s + M_ROWS * 128;        // 16 x 256
    float* s_y    = s_x + M_ROWS * 256;        // 16 x 256
    float* s_cost = s_y + M_ROWS * 256;        // 16

    const int tid = threadIdx.x;
    const int b0  = blockIdx.x * M_ROWS;

    for (int i = tid; i < M_ROWS * 128; i += 256) {
        int r = i >> 7, c = i & 127;
        s_s[i] = (c < S_DIM) ? s0[(b0 + r) * S_DIM + c] : 0.f;
    }
    if (tid < M_ROWS) s_cost[tid] = 0.f;
    __syncthreads();

    const int rr = tid >> 4;
    const int ll = tid & 15;

    for (int t = 0; t < T_STEPS - 1; t++) {
        // layer 1: s(16x100, padded to 128) @ W1^T -> s_y
        gemm_16x256<4, S_DIM, 128>(s_s, W1 + t * H_DIM * S_DIM, s_w, s_y, tid);
        __syncthreads();
        ln_relu(s_y, s_x, b1 + t * H_DIM, g1 + t * H_DIM, be1 + t * H_DIM, rr, ll);
        __syncthreads();
        // layer 2: x(16x256) @ W2^T -> s_y
        gemm_16x256<8, 256, 256>(s_x, W2 + t * H_DIM * H_DIM, s_w, s_y, tid);
        __syncthreads();
        ln_relu(s_y, s_x, b2 + t * H_DIM, g2 + t * H_DIM, be2 + t * H_DIM, rr, ll);
        __syncthreads();
        // output layer: x(16x256) @ Wo^T -> s_y[:, 0..99]
        gemm_16x100(s_x, Wo + t * C_DIM * H_DIM, s_w, s_y, tid);
        __syncthreads();

        // elementwise: a = min(policy + bo, s); cost += p*a + 0.01*(p*a)^2; s -= a
        {
            const float* p    = prices + ((size_t)(b0 + rr) * T_STEPS + t) * S_DIM;
            const float* bo_t = bo + t * C_DIM;
            float part = 0.f;
#pragma unroll
            for (int i2 = 0; i2 < 7; i2++) {
                int idx = ll + (i2 << 4);
                if (idx < S_DIM) {
                    float sv = s_s[rr * 128 + idx];
                    float a  = fminf(s_y[rr * 256 + idx] + bo_t[idx], sv);
                    float pa = p[idx] * a;
                    part += pa + 0.01f * pa * pa;
                    s_s[rr * 128 + idx] = sv - a;
                }
            }
#pragma unroll
            for (int o = 8; o >= 1; o >>= 1)
                part += __shfl_xor_sync(0xffffffffu, part, o);
            if (ll == 0) s_cost[rr] += part;
        }
        __syncthreads();
    }

    // terminal step: a = s
    {
        const float* p = prices + ((size_t)(b0 + rr) * T_STEPS + (T_STEPS - 1)) * S_DIM;
        float part = 0.f;
#pragma unroll
        for (int i2 = 0; i2 < 7; i2++) {
            int idx = ll + (i2 << 4);
            if (idx < S_DIM) {
                float sv = s_s[rr * 128 + idx];
                float pa = p[idx] * sv;
                part += pa + 0.01f * pa * pa;
            }
        }
#pragma unroll
        for (int o = 8; o >= 1; o >>= 1)
            part += __shfl_xor_sync(0xffffffffu, part, o);
        if (ll == 0) s_cost[rr] += part;
    }
    __syncthreads();
    if (tid == 0) {
        float tot = 0.f;
#pragma unroll
        for (int r = 0; r < M_ROWS; r++) tot += s_cost[r];
        g_partials[blockIdx.x] = tot;
    }
}

__global__ void reduce_kernel(float* __restrict__ out) {
    int tid = threadIdx.x;
    float v = g_partials[tid];
    __shared__ float sh[8];
#pragma unroll
    for (int o = 16; o >= 1; o >>= 1) v += __shfl_xor_sync(0xffffffffu, v, o);
    if ((tid & 31) == 0) sh[tid >> 5] = v;
    __syncthreads();
    if (tid == 0) {
        float tot = 0.f;
#pragma unroll
        for (int i = 0; i < 8; i++) tot += sh[i];
        out[0] = tot * (1.f / (float)B_ROWS);
    }
}

extern "C" void kernel_launch(void* const* d_in, const int* in_sizes, int n_in,
                              void* d_out, int out_size) {
    const float* s0     = (const float*)d_in[0];
    const float* prices = (const float*)d_in[1];
    const float* W1     = (const float*)d_in[2];
    const float* b1     = (const float*)d_in[3];
    const float* g1     = (const float*)d_in[4];
    const float* be1    = (const float*)d_in[5];
    const float* W2     = (const float*)d_in[6];
    const float* b2     = (const float*)d_in[7];
    const float* g2     = (const float*)d_in[8];
    const float* be2    = (const float*)d_in[9];
    const float* Wo     = (const float*)d_in[10];
    const float* bo     = (const float*)d_in[11];

    size_t smem = (size_t)(2 * WBUF + M_ROWS * 128 + 2 * M_ROWS * 256 + M_ROWS) * sizeof(float);
    cudaFuncSetAttribute(model_kernel, cudaFuncAttributeMaxDynamicSharedMemorySize, (int)smem);
    model_kernel<<<N_CTA, 256, smem>>>(s0, prices, W1, b1, g1, be1,
                                       W2, b2, g2, be2, Wo, bo);
    reduce_kernel<<<1, 256>>>((float*)d_out);
}